// round 14
// baseline (speedup 1.0000x reference)
#include <cuda_runtime.h>
#include <math.h>
#include <stdint.h>

#define BZ    8
#define IM    128
#define HW    (IM * IM)        // 16384
#define CIN   3

#define NWORK 512              // worker blocks: 64 per batch
#define NPASS BZ               // passthrough blocks
#define GROUP 64               // producer blocks per batch

// E[b][o][w] = leakyrelu(W @ S);  per-batch handshake counters (self-reset).
__device__ float g_E[BZ * IM * IM];
__device__ int   g_prod[BZ];
__device__ int   g_cons[BZ];

// ---------------------------------------------------------------------------
// Homogeneous fused kernel: every worker block produces 2 columns of E for its
// batch, then broadcasts 2 rows of the SAME batch (waits only on its own
// 64-block group -> deadlock-free at any residency).
// grid = 520 x 256 threads (8 warps).
// ---------------------------------------------------------------------------
__global__ void __launch_bounds__(256) fused_kernel(const float* __restrict__ x,
                                                    const float* __restrict__ conv_w,
                                                    float* __restrict__ out) {
    __shared__ float  sRe[2][IM], sIm[2][IM];          // 2 KB
    __shared__ float  sP[2][4][8][32];                 // 8 KB DFT partials
    __shared__ float4 sST4[2 * 32];                    // 1 KB S^T swizzled
    __shared__ float  t128c[IM], t128s[IM], t32c[32], t32s[32];   // 1.25 KB

    const int k   = blockIdx.x;
    const int tid = threadIdx.x;

    if (k >= NWORK) {
        // ---------------- passthrough: out[b,128,:,:] = x[b,2,:,:] ----------
        const int b = k - NWORK;
        float4*       d4  = (float4*)(out + (size_t)(b * (IM + 1) + IM) * HW);
        const float4* src = (const float4*)(x + (size_t)b * CIN * HW + 2 * HW);
#pragma unroll
        for (int j = tid; j < HW / 4; j += 256) d4[j] = src[j];
        return;
    }

    const int b    = k >> 6;           // batch
    const int wp   = k & 63;           // w-pair index
    const int w0   = wp * 2;           // columns w0, w0+1
    const int wid  = tid >> 5;         // 0..7
    const int lane = tid & 31;
    const int col  = wid >> 2;         // 0..1  local column
    const int q    = wid & 3;          // 0..3  t-quarter

    // ======================= PRODUCE: DFT + GEMM ==========================
    // Load 2 adjacent columns (both channels) as float2 per h-row.
    if (tid < 256) {
        int ch = tid >> 7, h = tid & 127;
        const float* xb = x + (size_t)b * CIN * HW + (size_t)ch * HW;
        float2 v = ((const float2*)xb)[h * (IM / 2) + wp];
        float (*dst)[IM] = ch ? sIm : sRe;
        dst[0][h] = v.x; dst[1][h] = v.y;
    }

    // Twiddle tables (exact).
    if (tid < 160) {
        float s, c;
        if (tid < 128) {
            sincosf(-6.283185307179586f * (float)tid * (1.0f / 128.0f), &s, &c);
            t128c[tid] = c; t128s[tid] = s;
        } else {
            int kk = tid - 128;
            sincosf(-6.283185307179586f * (float)kk * (1.0f / 32.0f), &s, &c);
            t32c[kk] = c; t32s[kk] = s;
        }
    }
    __syncthreads();

    // Partial radix-4 DFT: 8 t-steps, 16 FMA each (t in [8q, 8q+8)).
    {
        float A0r = 0, A0i = 0, A1r = 0, A1i = 0, A2r = 0, A2i = 0, A3r = 0, A3i = 0;
        const float4* r4 = (const float4*)sRe[col];
        const float4* m4 = (const float4*)sIm[col];

#pragma unroll
        for (int tt = 0; tt < 8; tt++) {
            int   t = q * 8 + tt;
            int   kk = (lane * t) & 31;
            float c = t32c[kk], s = t32s[kk];
            float4 xr = r4[t];
            float4 xm = m4[t];
            A0r = fmaf(xr.x, c, A0r); A0r = fmaf(-xm.x, s, A0r);
            A0i = fmaf(xr.x, s, A0i); A0i = fmaf( xm.x, c, A0i);
            A1r = fmaf(xr.y, c, A1r); A1r = fmaf(-xm.y, s, A1r);
            A1i = fmaf(xr.y, s, A1i); A1i = fmaf( xm.y, c, A1i);
            A2r = fmaf(xr.z, c, A2r); A2r = fmaf(-xm.z, s, A2r);
            A2i = fmaf(xr.z, s, A2i); A2i = fmaf( xm.z, c, A2i);
            A3r = fmaf(xr.w, c, A3r); A3r = fmaf(-xm.w, s, A3r);
            A3i = fmaf(xr.w, s, A3i); A3i = fmaf( xm.w, c, A3i);
        }
        sP[col][q][0][lane] = A0r; sP[col][q][1][lane] = A0i;
        sP[col][q][2][lane] = A1r; sP[col][q][3][lane] = A1i;
        sP[col][q][4][lane] = A2r; sP[col][q][5][lane] = A2i;
        sP[col][q][6][lane] = A3r; sP[col][q][7][lane] = A3i;
    }
    __syncthreads();

    // Combine partials; warp (col, q) produces output quarter q of its column.
    {
        float a[8];
#pragma unroll
        for (int v = 0; v < 8; v++)
            a[v] = sP[col][0][v][lane] + sP[col][1][v][lane]
                 + sP[col][2][v][lane] + sP[col][3][v][lane];

        float cw = t128c[lane],             sw = t128s[lane];
        float c2 = t128c[(2 * lane) & 127], s2 = t128s[(2 * lane) & 127];
        float c3 = t128c[(3 * lane) & 127], s3 = t128s[(3 * lane) & 127];

        float T0r = a[0],                  T0i = a[1];
        float T1r = cw * a[2] - sw * a[3], T1i = cw * a[3] + sw * a[2];
        float T2r = c2 * a[4] - s2 * a[5], T2i = c2 * a[5] + s2 * a[4];
        float T3r = c3 * a[6] - s3 * a[7], T3i = c3 * a[7] + s3 * a[6];

        float Er = T0r + T2r, Ei = T0i + T2i;
        float Fr = T1r + T3r, Fi = T1i + T3i;
        float Gr = T0r - T2r, Gi = T0i - T2i;
        float Hr = T1r - T3r, Hi = T1i - T3i;

        float mr, mi;                    // warp-uniform select on q
        if      (q == 0) { mr = Er + Fr; mi = Ei + Fi; }
        else if (q == 1) { mr = Gr + Hi; mi = Gi - Hr; }
        else if (q == 2) { mr = Er - Fr; mi = Ei - Fi; }
        else             { mr = Gr - Hi; mi = Gi + Hr; }

        float mag = sqrtf(mr * mr + mi * mi) * (1.0f / 128.0f);
        int   i   = lane + 32 * q;
        ((float*)sST4)[(col * 32 + ((i >> 2) ^ col)) * 4 + (i & 3)] = mag;
    }
    __syncthreads();

    // GEMM: 16 passes; warp handles o = pass*8 + wid.
    // lanes = (wloc = lane&1 [w], ksub = lane>>1 [k-split 0..15]).
    {
        const int wloc = lane & 1;
        const int ksub = lane >> 1;
        const float4* W4 = (const float4*)conv_w;

#pragma unroll 4
        for (int pass = 0; pass < 16; pass++) {
            int o = pass * 8 + wid;
            float acc = 0.0f;
#pragma unroll
            for (int j = 0; j < 2; j++) {
                int i4 = ksub * 2 + j;
                float4 wv = W4[o * 32 + i4];                   // L1-hot
                float4 sv = sST4[wloc * 32 + (i4 ^ wloc)];     // conflict-free
                acc = fmaf(wv.x, sv.x, acc); acc = fmaf(wv.y, sv.y, acc);
                acc = fmaf(wv.z, sv.z, acc); acc = fmaf(wv.w, sv.w, acc);
            }
            acc += __shfl_xor_sync(0xFFFFFFFF, acc, 2);
            acc += __shfl_xor_sync(0xFFFFFFFF, acc, 4);
            acc += __shfl_xor_sync(0xFFFFFFFF, acc, 8);
            acc += __shfl_xor_sync(0xFFFFFFFF, acc, 16);
            if (ksub == 0) {
                float e = (acc >= 0.0f) ? acc : 0.2f * acc;
                g_E[(size_t)(b * IM + o) * IM + w0 + wloc] = e;
            }
        }
    }

    // Publish.
    __threadfence();
    __syncthreads();
    if (tid == 0) atomicAdd(&g_prod[b], 1);

    // ======================= CONSUME: 2 rows of own batch ==================
    // Wait only on own group's 64 producers.
    if (tid == 0) {
        volatile int* p = g_prod + b;
        while (*p < GROUP) __nanosleep(64);
    }
    __syncthreads();
    __threadfence();                                   // acquire

#pragma unroll
    for (int r = 0; r < 2; r++) {
        int o = w0 + r;                                // rows 2wp, 2wp+1
        const float4* e4 = (const float4*)(g_E + (size_t)(b * IM + o) * IM);
        float4 v = __ldcg(e4 + (tid & 31));
        float4* out4 = (float4*)(out + (size_t)(b * (IM + 1) + o) * HW);
        const int w4 = tid & 31;
        const int h0 = tid >> 5;
#pragma unroll
        for (int h = h0; h < IM; h += 8) out4[h * (IM / 4) + w4] = v;
    }

    // Reset protocol: last of the 64 consumer blocks zeroes both counters.
    __syncthreads();
    if (tid == 0) {
        int old = atomicAdd(&g_cons[b], 1);
        if (old == GROUP - 1) {
            *(volatile int*)&g_prod[b] = 0;
            *(volatile int*)&g_cons[b] = 0;
        }
    }
}

// ---------------------------------------------------------------------------
extern "C" void kernel_launch(void* const* d_in, const int* in_sizes, int n_in,
                              void* d_out, int out_size) {
    const float* x      = (const float*)d_in[0];
    const float* conv_w = (const float*)d_in[2];
    float*       out    = (float*)d_out;

    fused_kernel<<<NWORK + NPASS, 256>>>(x, conv_w, out);
}